// round 15
// baseline (speedup 1.0000x reference)
#include <cuda_runtime.h>
#include <cuda_fp16.h>
#include <cstdint>

// PatchMerged fused: Haar-DWT2 + LayerNorm + (384->192) GEMM, fp16 mma.sync.
// Warp-specialized persistent CTAs: 4 producer warps (LDG/stats/cvt/STS, chunk-level
// register double-buffer) feed a 4-stage A ring; 8 consumer warps (2Mx4N) run
// ldmatrix+MMA only. Weight matrix resident in SMEM. Named-barrier pipeline.
// out[b, l, d] = r*(G - mu*s[d]) + t[d],  G = patch @ W4
//   mu = sum_c x[b,c,2h,2w]/192 ; var = sum_patch x^2/384 - mu^2  (Haar identities)

__device__ __align__(16) __half g_Wh[73728];   // 6 chunks x [192 n-rows x 64 k] swizzled
__device__ float2 g_st2[192];                  // (s,t) folded reduction vectors
__device__ int g_tilectr;                      // unused (kept for prep symmetry)

// ---- prep (merged): blocks <288 fold Haar+gamma into swizzled W4 image;
//      blocks >=288 compute per-d (s,t) ----
__global__ void pm_prep(const float* __restrict__ nw, const float* __restrict__ nb,
                        const float* __restrict__ wr) {
    if (blockIdx.x < 288) {
        int idx = blockIdx.x * 256 + threadIdx.x;
        if (idx >= 384 * 192) return;
        int kg = idx / 192, d = idx - kg * 192;
        int c = kg >> 2, q = kg & 3, dy = q >> 1, dx = q & 1;
        float wll = nw[c]       * wr[c * 192 + d];
        float wlh = nw[96 + c]  * wr[(96 + c) * 192 + d];
        float whl = nw[192 + c] * wr[(192 + c) * 192 + d];
        float whh = nw[288 + c] * wr[(288 + c) * 192 + d];
        float v = 0.5f * (wll + (dy ? -wlh : wlh) + (dx ? -whl : whl)
                              + ((dx ^ dy) ? -whh : whh));
        int ck = c >> 4, kl = ((c & 15) << 2) | q;       // chunk 0..5, k-local 0..63
        int off = ck * 24576 + d * 128 + ((((kl >> 3) ^ (d & 7)) << 4)) + (kl & 7) * 2;
        g_Wh[off >> 1] = __float2half_rn(v);
    } else {
        __shared__ float rs[8], rt[8];
        const int d = blockIdx.x - 288, tid = threadIdx.x;
        float s = 0.f, t = 0.f;
        for (int yc = tid; yc < 384; yc += 256) {
            float w = wr[yc * 192 + d];
            s += nw[yc] * w; t += nb[yc] * w;
        }
        #pragma unroll
        for (int o = 16; o > 0; o >>= 1) {
            s += __shfl_down_sync(0xffffffffu, s, o);
            t += __shfl_down_sync(0xffffffffu, t, o);
        }
        if ((tid & 31) == 0) { rs[tid >> 5] = s; rt[tid >> 5] = t; }
        __syncthreads();
        if (tid == 0) {
            float fs = 0.f, ft = 0.f;
            #pragma unroll
            for (int i = 0; i < 8; i++) { fs += rs[i]; ft += rt[i]; }
            g_st2[d] = make_float2(fs, ft);
        }
    }
}

__device__ __forceinline__ uint32_t smem_u32(const void* p) {
    uint32_t a;
    asm("{ .reg .u64 t; cvta.to.shared.u64 t, %1; cvt.u32.u64 %0, t; }" : "=r"(a) : "l"(p));
    return a;
}

#define BAR_SYNC(id, cnt)   asm volatile("bar.sync %0, %1;"   :: "r"(id), "r"(cnt) : "memory")
#define BAR_ARRIVE(id, cnt) asm volatile("bar.arrive %0, %1;" :: "r"(id), "r"(cnt) : "memory")
#define MEMBAR_CTA()        asm volatile("membar.cta;" ::: "memory")

// SMEM map (dynamic, 219648 B)
static constexpr int SM_W   = 0;         // 147456: weight image (6 chunks)
static constexpr int SM_A   = 147456;    // 4 x 16384: A fp16 ring (128r x 64k, swizzled)
static constexpr int SM_RED = 212992;    // 4x128 sums | 4x128 ssq (4096 B)
static constexpr int SM_MU  = 217088;    // 128 f32
static constexpr int SM_RR  = 217600;    // 128 f32
static constexpr int SM_ST  = 218112;    // 192 float2
static constexpr int SMEM_SZ = 219648;
static constexpr int NTILE = 2048;
// named barriers: full[s]=1+s, empty[s]=5+s, stats_full=9, stats_empty=10, prod=11
static constexpr int CNT_ALL = 384, CNT_PROD = 128;

// producer chunk load: warp pw owns channel-pairs {2pw, 2pw+1}; 16 float2 per slice
#define PLDG(buf, tt, kk) do {                                                         \
    int bb = (tt) >> 7, hh = (tt) & 127;                                               \
    _Pragma("unroll") for (int s01 = 0; s01 < 2; s01++)                                \
    _Pragma("unroll") for (int ci = 0; ci < 2; ci++)                                   \
    _Pragma("unroll") for (int dy = 0; dy < 2; dy++)                                   \
    _Pragma("unroll") for (int j = 0; j < 4; j++)                                      \
        pf[buf][s01][ci][dy][j] = *(const float2*)(x +                                 \
            (((size_t)bb * 96 + (kk) * 16 + 2 * (2 * pw + s01) + ci) * 256             \
             + 2 * hh + dy) * 256 + 2 * (lane + 32 * j));                              \
} while (0)

__global__ void __launch_bounds__(384, 1)
pm_main(const float* __restrict__ x, float* __restrict__ out) {
    extern __shared__ char smem[];
    const uint32_t sb = smem_u32(smem);
    const int tid = threadIdx.x, lane = tid & 31, wid = tid >> 5;

    // ---- stage full weight matrix + st table (all 384 threads) ----
    {
        unsigned long long g0 =
            (unsigned long long)__cvta_generic_to_global((const char*)g_Wh + tid * 16);
        #pragma unroll
        for (int i = 0; i < 24; i++)
            asm volatile("cp.async.cg.shared.global [%0], [%1], 16;"
                         :: "r"(sb + SM_W + tid * 16 + i * 6144),
                            "l"(g0 + (unsigned long long)i * 6144) : "memory");
        asm volatile("cp.async.commit_group;" ::: "memory");
        asm volatile("cp.async.wait_group 0;" ::: "memory");
    }
    if (tid < 192) *(float2*)(smem + SM_ST + tid * 8) = g_st2[tid];
    __syncthreads();

    const int t0 = blockIdx.x;

    if (wid >= 8) {
        // ================= PRODUCER (4 warps) =================
        const int pw = wid - 8;
        float2 pf[2][2][2][2][4];
        int g = 0;
        if (t0 < NTILE) PLDG(0, t0, 0);

        for (int t = t0; t < NTILE; t += 148) {
            float ssum[4] = {0, 0, 0, 0}, ssq[4] = {0, 0, 0, 0};
            #pragma unroll 1
            for (int ck = 0; ck < 6; ++ck, ++g) {
                const int buf = g & 1;
                // issue next chunk's loads (register double-buffer -> full-chunk distance)
                int nt = t, nc = ck + 1;
                if (nc == 6) { nt = t + 148; nc = 0; }
                if (nt < NTILE) PLDG(buf ^ 1, nt, nc);
                if (g >= 4) BAR_SYNC(5 + (g & 3), CNT_ALL);       // stage free?
                const uint32_t ab = sb + SM_A + (uint32_t)((g & 3) << 14);
                #pragma unroll
                for (int s01 = 0; s01 < 2; s01++) {
                    const int cc = 2 * pw + s01;
                    #pragma unroll
                    for (int j = 0; j < 4; j++) {
                        const int p = lane + 32 * j;
                        float2 v00 = pf[buf][s01][0][0][j], v01 = pf[buf][s01][0][1][j];
                        float2 v10 = pf[buf][s01][1][0][j], v11 = pf[buf][s01][1][1][j];
                        ssum[j] += v00.x + v10.x;
                        ssq[j]  += v00.x * v00.x + v00.y * v00.y + v01.x * v01.x
                                 + v01.y * v01.y + v10.x * v10.x + v10.y * v10.y
                                 + v11.x * v11.x + v11.y * v11.y;
                        __half2 h0 = __floats2half2_rn(v00.x, v00.y);
                        __half2 h1 = __floats2half2_rn(v01.x, v01.y);
                        __half2 h2 = __floats2half2_rn(v10.x, v10.y);
                        __half2 h3 = __floats2half2_rn(v11.x, v11.y);
                        asm volatile("st.shared.v4.b32 [%0], {%1,%2,%3,%4};"
                                     :: "r"(ab + p * 128 + ((cc ^ (p & 7)) << 4)),
                                        "r"(*(uint32_t*)&h0), "r"(*(uint32_t*)&h1),
                                        "r"(*(uint32_t*)&h2), "r"(*(uint32_t*)&h3)
                                     : "memory");
                    }
                }
                MEMBAR_CTA();
                BAR_ARRIVE(1 + (g & 3), CNT_ALL);                 // stage full
            }
            // ---- LN stats finalize (producers own it) ----
            #pragma unroll
            for (int j = 0; j < 4; j++) {
                int p = lane + 32 * j;
                *(float*)(smem + SM_RED + (pw * 128 + p) * 4)        = ssum[j];
                *(float*)(smem + SM_RED + 2048 + (pw * 128 + p) * 4) = ssq[j];
            }
            BAR_SYNC(11, CNT_PROD);                               // producer-internal
            if (t != t0) BAR_SYNC(10, CNT_ALL);                   // prev mu/rr consumed?
            {
                const int p = tid - 256;                          // 0..127 = pixel
                float s = 0.f, qq = 0.f;
                #pragma unroll
                for (int w = 0; w < 4; w++) {
                    s  += *(float*)(smem + SM_RED + (w * 128 + p) * 4);
                    qq += *(float*)(smem + SM_RED + 2048 + (w * 128 + p) * 4);
                }
                float mu = s * (1.f / 192.f);
                float var = qq * (1.f / 384.f) - mu * mu;
                *(float*)(smem + SM_MU + p * 4) = mu;
                *(float*)(smem + SM_RR + p * 4) = rsqrtf(var + 1e-5f);
            }
            MEMBAR_CTA();
            BAR_ARRIVE(9, CNT_ALL);                               // stats ready
        }
    } else {
        // ================= CONSUMER (8 warps, 2M x 4N) =================
        const int gid = lane >> 2, t4 = lane & 3;
        const int wh = wid >> 2, cpn = wid & 3;
        const int l7 = lane & 7;
        const uint32_t arow_off = (uint32_t)((wh * 64 + l7 + ((lane >> 3) & 1) * 8) * 128);
        const uint32_t brow_off = (uint32_t)((cpn * 48 + l7 + (lane >> 4) * 8) * 128);
        const int ga_sel = lane >> 4, gb_sel = (lane >> 3) & 1;
        int g = 0;

        for (int t = t0; t < NTILE; t += 148) {
            const int b = t >> 7, h = t & 127;
            float acc[4][6][4];
            #pragma unroll
            for (int i = 0; i < 4; i++)
            #pragma unroll
            for (int j = 0; j < 6; j++)
            #pragma unroll
            for (int q = 0; q < 4; q++) acc[i][j][q] = 0.f;

            #pragma unroll 1
            for (int ck = 0; ck < 6; ++ck, ++g) {
                BAR_SYNC(1 + (g & 3), CNT_ALL);                   // stage full?
                const uint32_t abuf = sb + SM_A + (uint32_t)((g & 3) << 14);
                const uint32_t wck = sb + SM_W + (uint32_t)(ck * 24576);
                #pragma unroll
                for (int s = 0; s < 4; s++) {
                    uint32_t ua[4][4], ub[6][2];
                    const uint32_t xa = (uint32_t)((((2 * s + ga_sel) ^ l7)) << 4);
                    const uint32_t xb = (uint32_t)((((2 * s + gb_sel) ^ l7)) << 4);
                    #pragma unroll
                    for (int mt = 0; mt < 4; mt++)
                        asm volatile(
                            "ldmatrix.sync.aligned.m8n8.x4.shared.b16 {%0,%1,%2,%3}, [%4];"
                            : "=r"(ua[mt][0]), "=r"(ua[mt][1]),
                              "=r"(ua[mt][2]), "=r"(ua[mt][3])
                            : "r"(abuf + arow_off + mt * 2048 + xa));
                    #pragma unroll
                    for (int p = 0; p < 3; p++)
                        asm volatile(
                            "ldmatrix.sync.aligned.m8n8.x4.shared.b16 {%0,%1,%2,%3}, [%4];"
                            : "=r"(ub[2 * p][0]), "=r"(ub[2 * p][1]),
                              "=r"(ub[2 * p + 1][0]), "=r"(ub[2 * p + 1][1])
                            : "r"(wck + brow_off + p * 2048 + xb));
                    #pragma unroll
                    for (int mt = 0; mt < 4; mt++)
                    #pragma unroll
                    for (int nt = 0; nt < 6; nt++)
                        asm volatile(
                            "mma.sync.aligned.m16n8k16.row.col.f32.f16.f16.f32 "
                            "{%0,%1,%2,%3}, {%4,%5,%6,%7}, {%8,%9}, {%0,%1,%2,%3};"
                            : "+f"(acc[mt][nt][0]), "+f"(acc[mt][nt][1]),
                              "+f"(acc[mt][nt][2]), "+f"(acc[mt][nt][3])
                            : "r"(ua[mt][0]), "r"(ua[mt][1]), "r"(ua[mt][2]), "r"(ua[mt][3]),
                              "r"(ub[nt][0]), "r"(ub[nt][1]));
                }
                BAR_ARRIVE(5 + (g & 3), CNT_ALL);                 // stage free
            }

            BAR_SYNC(9, CNT_ALL);                                 // mu/rr ready
            float* ob = out + ((size_t)b * 16384 + (size_t)h * 128) * 192;
            #pragma unroll
            for (int mt = 0; mt < 4; mt++) {
                int row0 = wh * 64 + mt * 16 + gid;
                float mu0 = *(float*)(smem + SM_MU + row0 * 4);
                float r0  = *(float*)(smem + SM_RR + row0 * 4);
                float mu1 = *(float*)(smem + SM_MU + (row0 + 8) * 4);
                float r1  = *(float*)(smem + SM_RR + (row0 + 8) * 4);
                #pragma unroll
                for (int nt = 0; nt < 6; nt++) {
                    int cb = cpn * 48 + nt * 8 + 2 * t4;
                    float2 st0 = *(const float2*)(smem + SM_ST + cb * 8);
                    float2 st1 = *(const float2*)(smem + SM_ST + cb * 8 + 8);
                    float2 v0, v1;
                    v0.x = r0 * (acc[mt][nt][0] - mu0 * st0.x) + st0.y;
                    v0.y = r0 * (acc[mt][nt][1] - mu0 * st1.x) + st1.y;
                    v1.x = r1 * (acc[mt][nt][2] - mu1 * st0.x) + st0.y;
                    v1.y = r1 * (acc[mt][nt][3] - mu1 * st1.x) + st1.y;
                    *(float2*)(ob + (size_t)row0 * 192 + cb)       = v0;
                    *(float2*)(ob + (size_t)(row0 + 8) * 192 + cb) = v1;
                }
            }
            BAR_ARRIVE(10, CNT_ALL);                              // mu/rr consumed
        }
    }
}

extern "C" void kernel_launch(void* const* d_in, const int* in_sizes, int n_in,
                              void* d_out, int out_size) {
    const float* x  = (const float*)d_in[0];
    const float* nw = (const float*)d_in[1];
    const float* nb = (const float*)d_in[2];
    const float* wr = (const float*)d_in[3];
    float* out = (float*)d_out;
    (void)in_sizes; (void)n_in; (void)out_size;

    static int cfg = 0;
    if (!cfg) {
        cudaFuncSetAttribute(pm_main, cudaFuncAttributeMaxDynamicSharedMemorySize, SMEM_SZ);
        cfg = 1;
    }
    pm_prep<<<480, 256>>>(nw, nb, wr);
    pm_main<<<148, 384, SMEM_SZ>>>(x, out);
}